// round 5
// baseline (speedup 1.0000x reference)
#include <cuda_runtime.h>
#include <stdint.h>

#define HH 256
#define WW 256
#define NPIX (HH*WW)

// packed rank table: (spiral_rank(s) << 6) | s   for s = (dj+3)*7 + (di+3)
__constant__ int c_rank[49] = {
    (42<<6)|0,(43<<6)|1,(44<<6)|2,(45<<6)|3,(46<<6)|4,(47<<6)|5,(48<<6)|6,
    (41<<6)|7,(20<<6)|8,(21<<6)|9,(22<<6)|10,(23<<6)|11,(24<<6)|12,(25<<6)|13,
    (40<<6)|14,(19<<6)|15,(6<<6)|16,(7<<6)|17,(8<<6)|18,(9<<6)|19,(26<<6)|20,
    (39<<6)|21,(18<<6)|22,(5<<6)|23,(0<<6)|24,(1<<6)|25,(10<<6)|26,(27<<6)|27,
    (38<<6)|28,(17<<6)|29,(4<<6)|30,(3<<6)|31,(2<<6)|32,(11<<6)|33,(28<<6)|34,
    (37<<6)|35,(16<<6)|36,(15<<6)|37,(14<<6)|38,(13<<6)|39,(12<<6)|40,(29<<6)|41,
    (36<<6)|42,(35<<6)|43,(34<<6)|44,(33<<6)|45,(32<<6)|46,(31<<6)|47,(30<<6)|48
};

__device__ __forceinline__ float imload(const float* __restrict__ img, int y, int x) {
    y = min(max(y, 0), HH - 1);
    x = min(max(x, 0), WW - 1);
    return __ldg(&img[y * WW + x]);
}

__device__ __forceinline__ unsigned char quant(float v) {
    float r = rintf(v * 255.0f);          // round half-to-even, matches jnp.round
    r = fminf(fmaxf(r, 0.0f), 255.0f);
    return (unsigned char)r;
}

__device__ __forceinline__ void mnmx(float& a, float& b) {
    float t = fminf(a, b);
    b = fmaxf(a, b);
    a = t;
}
__device__ __forceinline__ float median9(float p0, float p1, float p2,
                                         float p3, float p4, float p5,
                                         float p6, float p7, float p8) {
    mnmx(p1, p2); mnmx(p4, p5); mnmx(p7, p8);
    mnmx(p0, p1); mnmx(p3, p4); mnmx(p6, p7);
    mnmx(p1, p2); mnmx(p4, p5); mnmx(p7, p8);
    mnmx(p0, p3); mnmx(p5, p8); mnmx(p4, p7);
    mnmx(p3, p6); mnmx(p1, p4); mnmx(p2, p5);
    mnmx(p4, p7); mnmx(p4, p2); mnmx(p6, p4);
    mnmx(p4, p2);
    return p4;
}

// =====================================================================
// Single fused kernel: binomial -> quantize -> gradient -> block match
// -> subpixel -> median -> bilateral.  16x16 output tile per block;
// flow computed on a 22x22 region (halo 3) at clamped coordinates
// (== replicate padding for the median stage).
// =====================================================================
__global__ __launch_bounds__(512, 2) void flow_kernel(const float* __restrict__ f,
                                                      const float* __restrict__ g,
                                                      float* __restrict__ out) {
    // f pipeline
    __shared__ float rawf[34][34];            // origin (by-9, bx-9)
    __shared__ float vertf[32][34];           // rows (by-8), cols (bx-9)
    __shared__ float sfb[32][32];             // origin (by-8, bx-8)
    __shared__ __align__(16) unsigned char sfq[32][40];   // cols 32..39 zero
    __shared__ uint32_t sfqs[32][4][13];      // shifted copies; words 0..8 used
    // g pipeline
    __shared__ float rawg[28][28];            // origin (by-6, bx-6)
    __shared__ float vertg[26][28];           // rows (by-5), cols (bx-6)
    __shared__ __align__(16) unsigned char sgq[26][28];   // origin (by-5, bx-5)
    // gradients of fb on (by-5, bx-5) .. 26x26, zero outside image
    __shared__ float sdx[26][26];
    __shared__ float sdy[26][26];
    // flow on (by-3, bx-3) .. 22x22 (clamped pixels)
    __shared__ float sflow0[22][22];
    __shared__ float sflow1[22][22];
    // median + guide on (by-2, bx-2) .. 20x20, zero outside image
    __shared__ float smed0[20][20];
    __shared__ float smed1[20][20];
    __shared__ float sguide[20][20];

    const int bx = blockIdx.x * 16, by = blockIdx.y * 16;
    const int tid = threadIdx.x;

    // ---- phase 1: raw loads (replicate clamp) ----
    for (int i = tid; i < 34 * 34; i += 512) {
        int r = i / 34, c = i % 34;
        rawf[r][c] = imload(f, by - 9 + r, bx - 9 + c);
    }
    for (int i = tid; i < 28 * 28; i += 512) {
        int r = i / 28, c = i % 28;
        rawg[r][c] = imload(g, by - 6 + r, bx - 6 + c);
    }
    __syncthreads();

    // ---- phase 2: vertical binomial ----
    for (int i = tid; i < 32 * 34; i += 512) {
        int r = i / 34, c = i % 34;
        vertf[r][c] = (rawf[r][c] + 2.0f * rawf[r + 1][c] + rawf[r + 2][c]) * 0.25f;
    }
    for (int i = tid; i < 26 * 28; i += 512) {
        int r = i / 28, c = i % 28;
        vertg[r][c] = (rawg[r][c] + 2.0f * rawg[r + 1][c] + rawg[r + 2][c]) * 0.25f;
    }
    __syncthreads();

    // ---- phase 3: horizontal binomial + quantize ----
    for (int i = tid; i < 32 * 40; i += 512) {
        int r = i / 40, c = i % 40;
        unsigned char v = 0;
        if (c < 32) {
            float fb = (vertf[r][c] + 2.0f * vertf[r][c + 1] + vertf[r][c + 2]) * 0.25f;
            sfb[r][c] = fb;
            int y = by - 8 + r, x = bx - 8 + c;
            bool in = (y >= 0 && y < HH && x >= 0 && x < WW);
            v = in ? quant(fb) : (unsigned char)0;
        }
        sfq[r][c] = v;
    }
    for (int i = tid; i < 26 * 28; i += 512) {
        int r = i / 28, c = i % 28;
        unsigned char v = 0;
        if (c < 26) {
            float gb = (vertg[r][c] + 2.0f * vertg[r][c + 1] + vertg[r][c + 2]) * 0.25f;
            int y = by - 5 + r, x = bx - 5 + c;
            bool in = (y >= 0 && y < HH && x >= 0 && x < WW);
            v = in ? quant(gb) : (unsigned char)0;
        }
        sgq[r][c] = v;
    }
    __syncthreads();

    // ---- phase 4: shifted fq copies (conflict-free layout) + gradient ----
    for (int i = tid; i < 32 * 36; i += 512) {     // 32 rows x (4 shifts x 9 words)
        int r = i / 36, rem = i % 36;
        int k = rem / 9, w = rem % 9;
        const uint32_t* W = (const uint32_t*)sfq[r];
        sfqs[r][k][w] = __byte_perm(W[w], W[w + 1], 0x3210u + (unsigned)k * 0x1111u);
    }
    for (int i = tid; i < 26 * 26; i += 512) {
        int r = i / 26, c = i % 26;
        int y = by - 5 + r, x = bx - 5 + c;
        bool in = (y >= 0 && y < HH && x >= 0 && x < WW);
        float dyv = 0.0f, dxv = 0.0f;
        if (in) {
            int yn = min(y + 1, HH - 1) - (by - 8);
            int yp = max(y - 1, 0) - (by - 8);
            int xn = min(x + 1, WW - 1) - (bx - 8);
            int xp = max(x - 1, 0) - (bx - 8);
            dyv = (sfb[yn][c + 3] - sfb[yp][c + 3]) * 0.5f;
            dxv = (sfb[r + 3][xn] - sfb[r + 3][xp]) * 0.5f;
        }
        sdy[r][c] = dyv;
        sdx[r][c] = dxv;
    }
    __syncthreads();

    // ---- phase 5: block match + subpixel on the 22x22 flow region ----
    if (tid < 484) {
        int rF = tid / 22, cF = tid % 22;
        int py = min(max(by - 3 + rF, 0), HH - 1);    // clamped pixel (replicate)
        int px = min(max(bx - 3 + cF, 0), WW - 1);
        int ly = py - by;                 // [-3, 18]
        int lx = px - (bx - 8);           // [5, 26]
        int lgy = py - (by - 5);          // [2, 23]
        int lgx = px - (bx - 5);
        int row0 = ly + 3;                // [0, 21]

        // g template: 5 rows (4 bytes + 1 byte)
        unsigned int glo[5], ghib[5];
        {
            int o2 = lgx - 2;
            int k2 = o2 & 3, w2 = o2 >> 2;
            unsigned int sel = 0x3210u + (unsigned)k2 * 0x1111u;
            #pragma unroll
            for (int ky = 0; ky < 5; ky++) {
                const uint32_t* row = (const uint32_t*)sgq[lgy - 2 + ky];
                uint32_t a = row[w2], b2 = row[w2 + 1];
                glo[ky]  = __byte_perm(a, b2, sel);
                ghib[ky] = (b2 >> (8 * k2)) & 0xFFu;
            }
        }

        int best = 0x7fffffff;
        #pragma unroll 1
        for (int dip = 0; dip < 7; ++dip) {
            int s = lx + dip - 5;             // byte window start, [0, 27]
            int k = s & 3, wi = s >> 2;
            const uint32_t* bp = &sfqs[row0][k][wi];
            uint32_t flo[11], fhi[11];
            #pragma unroll
            for (int r = 0; r < 11; r++) {
                const uint32_t* rp = bp + r * 52;   // next fq row = 4*13 words
                flo[r] = rp[0];
                fhi[r] = rp[1] & 0xFFu;
            }
            #pragma unroll
            for (int djp = 0; djp < 7; djp++) {
                unsigned int sad = 0;
                #pragma unroll
                for (int ky = 0; ky < 5; ky++) {
                    sad = __dp4a(__vabsdiffu4(flo[djp + ky], glo[ky]), 0x01010101u, sad);
                    sad = __usad(fhi[djp + ky], ghib[ky], sad);
                }
                int packed = ((int)sad << 12) | c_rank[djp * 7 + dip];
                best = min(best, packed);
            }
        }
        int bestS = best & 63;
        int bjp = bestS / 7, bip = bestS % 7;

        // Lucas-Kanade subpixel on the 5x5 border ring
        float a = 0.f, b = 0.f, d = 0.f, pp = 0.f, q = 0.f;
        #pragma unroll
        for (int ky = 0; ky < 5; ky++) {
            #pragma unroll
            for (int kx = 0; kx < 5; kx++) {
                if (ky == 0 || ky == 4 || kx == 0 || kx == 4) {
                    float dx = sdx[lgy - 2 + ky][lgx - 2 + kx];
                    float dy = sdy[lgy - 2 + ky][lgx - 2 + kx];
                    float fv = (float)sfq[row0 + bjp + ky][lx + bip + kx - 5] * (1.0f / 255.0f);
                    unsigned int gb = (kx < 4) ? ((glo[ky] >> (8 * kx)) & 0xFFu) : ghib[ky];
                    float gv = (float)gb * (1.0f / 255.0f);
                    float zd = gv - fv;
                    a  += dx * dx;
                    b  += dx * dy;
                    d  += dy * dy;
                    pp += zd * dx;
                    q  += zd * dy;
                }
            }
        }
        // avoid FMA contraction: thresholds must match the reference rounding
        float det = __fsub_rn(__fmul_rn(a, d), __fmul_rn(b, b));
        float u   = __fsub_rn(__fmul_rn(d, pp), __fmul_rn(b, q));
        float v   = __fsub_rn(__fmul_rn(a, q), __fmul_rn(b, pp));
        bool bad = (det <= 1e-7f);
        float dd = bad ? 1.0f : det;
        float sv = v / dd;   // y component
        float su = u / dd;   // x component
        if (bad || fabsf(sv) >= 1.0f) sv = 0.0f;
        if (bad || fabsf(su) >= 1.0f) su = 0.0f;

        sflow0[rF][cF] = (float)(3 - bjp) + sv;   // -dj
        sflow1[rF][cF] = (float)(3 - bip) + su;   // -di
    }
    __syncthreads();

    // ---- phase 6: 3x3 median (replicate) + guide staging on 20x20 ----
    for (int i = tid; i < 20 * 20; i += 512) {
        int rM = i / 20, cM = i % 20;
        int y = by - 2 + rM, x = bx - 2 + cM;
        bool in = (y >= 0 && y < HH && x >= 0 && x < WW);
        float m0 = 0.0f, m1 = 0.0f, gd = 0.0f;
        if (in) {
            int ym = max(y - 1, 0) - (by - 3);
            int y0 = y - (by - 3);
            int yp = min(y + 1, HH - 1) - (by - 3);
            int xm = max(x - 1, 0) - (bx - 3);
            int x0 = x - (bx - 3);
            int xp = min(x + 1, WW - 1) - (bx - 3);
            m0 = median9(sflow0[ym][xm], sflow0[ym][x0], sflow0[ym][xp],
                         sflow0[y0][xm], sflow0[y0][x0], sflow0[y0][xp],
                         sflow0[yp][xm], sflow0[yp][x0], sflow0[yp][xp]);
            m1 = median9(sflow1[ym][xm], sflow1[ym][x0], sflow1[ym][xp],
                         sflow1[y0][xm], sflow1[y0][x0], sflow1[y0][xp],
                         sflow1[yp][xm], sflow1[yp][x0], sflow1[yp][xp]);
            gd = sfb[rM + 6][cM + 6];
        }
        smed0[rM][cM] = m0;
        smed1[rM][cM] = m1;
        sguide[rM][cM] = gd;
    }
    __syncthreads();

    // ---- phase 7: bilateral smoothing (zero pad) + output ----
    if (tid < 512) {
        int p = tid >> 1, ch = tid & 1;
        int ty = p >> 4, tx = p & 15;
        const float KVAL = -1.0f / 4.5f;   // -1/(2*1.5^2)
        const float SII  = 200.0f;         //  1/(2*0.05^2)
        float c = sguide[ty + 2][tx + 2];
        float wsum = 0.f, s = 0.f;
        const float (*md)[20] = ch ? smed1 : smed0;
        #pragma unroll
        for (int dy = 0; dy < 5; dy++) {
            #pragma unroll
            for (int dx = 0; dx < 5; dx++) {
                float tn = sguide[ty + dy][tx + dx];   // zero outside image
                float df = c - tn;
                float co = 1.0f - fabsf(KVAL - df * df * SII);
                co = fminf(fmaxf(co, 0.0f), 1.0f);
                wsum += co;                            // OOB still weighs denom
                s += md[ty + dy][tx + dx] * co;
            }
        }
        int y = by + ty, x = bx + tx;
        out[ch * NPIX + y * WW + x] = s / wsum;
    }
}

// ---------------- launch ----------------
extern "C" void kernel_launch(void* const* d_in, const int* in_sizes, int n_in,
                              void* d_out, int out_size) {
    const float* f = (const float*)d_in[0];
    const float* g = (const float*)d_in[1];
    float* out = (float*)d_out;

    dim3 grd(WW / 16, HH / 16);
    flow_kernel<<<grd, 512>>>(f, g, out);
}

// round 6
// speedup vs baseline: 1.1045x; 1.1045x over previous
#include <cuda_runtime.h>
#include <stdint.h>

#define HH 256
#define WW 256
#define NPIX (HH*WW)
#define NBLK 256u

// ---------------- scratch (device globals; no allocations allowed) -------------
__device__ float g_fb[NPIX];        // binomial-filtered f (guide for bilateral)
__device__ float g_flow1[2*NPIX];   // vector + subpixel (before median)
__device__ unsigned int g_bar;      // grid barrier counter (monotonic across replays)

// packed rank table: (spiral_rank(s) << 6) | s   for s = (dj+3)*7 + (di+3)
__constant__ int c_rank[49] = {
    (42<<6)|0,(43<<6)|1,(44<<6)|2,(45<<6)|3,(46<<6)|4,(47<<6)|5,(48<<6)|6,
    (41<<6)|7,(20<<6)|8,(21<<6)|9,(22<<6)|10,(23<<6)|11,(24<<6)|12,(25<<6)|13,
    (40<<6)|14,(19<<6)|15,(6<<6)|16,(7<<6)|17,(8<<6)|18,(9<<6)|19,(26<<6)|20,
    (39<<6)|21,(18<<6)|22,(5<<6)|23,(0<<6)|24,(1<<6)|25,(10<<6)|26,(27<<6)|27,
    (38<<6)|28,(17<<6)|29,(4<<6)|30,(3<<6)|31,(2<<6)|32,(11<<6)|33,(28<<6)|34,
    (37<<6)|35,(16<<6)|36,(15<<6)|37,(14<<6)|38,(13<<6)|39,(12<<6)|40,(29<<6)|41,
    (36<<6)|42,(35<<6)|43,(34<<6)|44,(33<<6)|45,(32<<6)|46,(31<<6)|47,(30<<6)|48
};

__device__ __forceinline__ float imload(const float* __restrict__ img, int y, int x) {
    y = min(max(y, 0), HH - 1);
    x = min(max(x, 0), WW - 1);
    return __ldg(&img[y * WW + x]);
}

__device__ __forceinline__ unsigned char quant(float v) {
    float r = rintf(v * 255.0f);          // round half-to-even, matches jnp.round
    r = fminf(fmaxf(r, 0.0f), 255.0f);
    return (unsigned char)r;
}

__device__ __forceinline__ void mnmx(float& a, float& b) {
    float t = fminf(a, b);
    b = fmaxf(a, b);
    a = t;
}
__device__ __forceinline__ float median9(float p0, float p1, float p2,
                                         float p3, float p4, float p5,
                                         float p6, float p7, float p8) {
    mnmx(p1, p2); mnmx(p4, p5); mnmx(p7, p8);
    mnmx(p0, p1); mnmx(p3, p4); mnmx(p6, p7);
    mnmx(p1, p2); mnmx(p4, p5); mnmx(p7, p8);
    mnmx(p0, p3); mnmx(p5, p8); mnmx(p4, p7);
    mnmx(p3, p6); mnmx(p1, p4); mnmx(p2, p5);
    mnmx(p4, p7); mnmx(p4, p2); mnmx(p6, p4);
    mnmx(p4, p2);
    return p4;
}

// shared-memory layouts for the two phases, overlaid
struct SmemA {
    float rawf[28][28];                       // origin (by-6,bx-6)
    float vertf[26][28];
    float sfb[26][26];                        // origin (by-5,bx-5)
    alignas(16) unsigned char sfq[26][32];    // cols 26..31 zero
    alignas(16) uint32_t sfqs[26][4][13];     // shifted copies, words 0..6 used
    float rawg[22][22];                       // origin (by-3,bx-3)
    float vertg[20][22];
    alignas(16) unsigned char sgq[20][24];    // origin (by-2,bx-2)
    float sdx[20][20];
    float sdy[20][20];
};
struct SmemB {
    float sflow[2][22][22];   // flow halo 3, replicate clamp
    float smed[2][20][20];    // median flow, halo 2, zero outside image
    float sguide[20][20];     // fb guide, halo 2, zero outside image
};

// =====================================================================
// One fused kernel with a software grid barrier between match & smooth.
// All 256 blocks are co-resident (512 thr, <=64 regs, ~23KB smem -> 2/SM).
// =====================================================================
__global__ __launch_bounds__(512, 2) void flow_fused(const float* __restrict__ f,
                                                     const float* __restrict__ g,
                                                     float* __restrict__ out) {
    __shared__ __align__(16) unsigned char smem_raw[
        sizeof(SmemA) > sizeof(SmemB) ? sizeof(SmemA) : sizeof(SmemB)];
    SmemA& A = *reinterpret_cast<SmemA*>(smem_raw);

    const int bx = blockIdx.x * 16, by = blockIdx.y * 16;
    const int tid = threadIdx.x;
    const int p  = tid >> 1;          // pixel 0..255
    const int z  = tid & 1;           // dip-group
    const int ty = p >> 4, tx = p & 15;

    // ================= PHASE A: binomial/quantize/gradient/match/subpixel =====
    for (int i = tid; i < 28 * 28; i += 512) {
        int r = i / 28, c = i % 28;
        A.rawf[r][c] = imload(f, by - 6 + r, bx - 6 + c);
    }
    for (int i = tid; i < 22 * 22; i += 512) {
        int r = i / 22, c = i % 22;
        A.rawg[r][c] = imload(g, by - 3 + r, bx - 3 + c);
    }
    __syncthreads();

    for (int i = tid; i < 26 * 28; i += 512) {
        int r = i / 28, c = i % 28;
        A.vertf[r][c] = (A.rawf[r][c] + 2.0f * A.rawf[r + 1][c] + A.rawf[r + 2][c]) * 0.25f;
    }
    for (int i = tid; i < 20 * 22; i += 512) {
        int r = i / 22, c = i % 22;
        A.vertg[r][c] = (A.rawg[r][c] + 2.0f * A.rawg[r + 1][c] + A.rawg[r + 2][c]) * 0.25f;
    }
    __syncthreads();

    for (int i = tid; i < 26 * 32; i += 512) {
        int r = i / 32, c = i % 32;
        unsigned char v = 0;
        if (c < 26) {
            float fb = (A.vertf[r][c] + 2.0f * A.vertf[r][c + 1] + A.vertf[r][c + 2]) * 0.25f;
            A.sfb[r][c] = fb;
            int y = by - 5 + r, x = bx - 5 + c;
            bool in = (y >= 0 && y < HH && x >= 0 && x < WW);
            v = in ? quant(fb) : (unsigned char)0;
        }
        A.sfq[r][c] = v;
    }
    for (int i = tid; i < 20 * 24; i += 512) {
        int r = i / 24, c = i % 24;
        unsigned char v = 0;
        if (c < 20) {
            float gb = (A.vertg[r][c] + 2.0f * A.vertg[r][c + 1] + A.vertg[r][c + 2]) * 0.25f;
            int y = by - 2 + r, x = bx - 2 + c;
            bool in = (y >= 0 && y < HH && x >= 0 && x < WW);
            v = in ? quant(gb) : (unsigned char)0;
        }
        A.sgq[r][c] = v;
    }
    __syncthreads();

    for (int i = tid; i < 26 * 28; i += 512) {
        int r = i / 28, rem = i % 28;
        int k = rem / 7, w = rem % 7;
        const uint32_t* W = (const uint32_t*)A.sfq[r];
        A.sfqs[r][k][w] = __byte_perm(W[w], W[w + 1], 0x3210u + (unsigned)k * 0x1111u);
    }
    for (int i = tid; i < 20 * 20; i += 512) {
        int r = i / 20, c = i % 20;
        int y = by - 2 + r, x = bx - 2 + c;
        bool in = (y >= 0 && y < HH && x >= 0 && x < WW);
        float dyv = 0.0f, dxv = 0.0f;
        if (in) {
            int yn = min(y + 1, HH - 1) - (by - 5);
            int yp = max(y - 1, 0) - (by - 5);
            int xn = min(x + 1, WW - 1) - (bx - 5);
            int xp = max(x - 1, 0) - (bx - 5);
            dyv = (A.sfb[yn][c + 3] - A.sfb[yp][c + 3]) * 0.5f;
            dxv = (A.sfb[r + 3][xn] - A.sfb[r + 3][xp]) * 0.5f;
        }
        A.sdy[r][c] = dyv;
        A.sdx[r][c] = dxv;
    }
    __syncthreads();

    // g template: 5 rows (4 bytes + 1 byte), origin col tx in sgq
    unsigned int glo[5], ghib[5];
    {
        int k2 = tx & 3, w2 = tx >> 2;
        unsigned int sel = 0x3210u + (unsigned)k2 * 0x1111u;
        #pragma unroll
        for (int ky = 0; ky < 5; ky++) {
            const uint32_t* row = (const uint32_t*)A.sgq[ty + ky];
            uint32_t a = row[w2], b2 = row[w2 + 1];
            glo[ky]  = __byte_perm(a, b2, sel);
            ghib[ky] = (b2 >> (8 * k2)) & 0xFFu;
        }
    }

    // SAD over assigned dip columns, conflict-free shifted-copy loads
    int best = 0x7fffffff;
    const int dip0 = z ? 4 : 0;
    const int dip1 = z ? 7 : 4;
    for (int dip = dip0; dip < dip1; ++dip) {
        int s = tx + dip;
        int k = s & 3, wi = s >> 2;
        const uint32_t* bp = &A.sfqs[ty][k][wi];
        uint32_t flo[11], fhi[11];
        #pragma unroll
        for (int r = 0; r < 11; r++) {
            const uint32_t* rp = bp + r * 52;   // next fq row = 4*13 words
            flo[r] = rp[0];
            fhi[r] = rp[1] & 0xFFu;
        }
        #pragma unroll
        for (int djp = 0; djp < 7; djp++) {
            unsigned int sad = 0;
            #pragma unroll
            for (int ky = 0; ky < 5; ky++) {
                sad = __dp4a(__vabsdiffu4(flo[djp + ky], glo[ky]), 0x01010101u, sad);
                sad = __usad(fhi[djp + ky], ghib[ky], sad);
            }
            int packed = ((int)sad << 12) | c_rank[djp * 7 + dip];
            best = min(best, packed);
        }
    }
    best = min(best, __shfl_xor_sync(0xffffffffu, best, 1));

    int bestS = best & 63;
    int bjp = bestS / 7, bip = bestS % 7;

    // Lucas-Kanade subpixel on the 5x5 border ring
    float a = 0.f, b = 0.f, d = 0.f, pp = 0.f, q = 0.f;
    #pragma unroll
    for (int ky = 0; ky < 5; ky++) {
        #pragma unroll
        for (int kx = 0; kx < 5; kx++) {
            if (ky == 0 || ky == 4 || kx == 0 || kx == 4) {
                float dx = A.sdx[ty + ky][tx + kx];
                float dy = A.sdy[ty + ky][tx + kx];
                float fv = (float)A.sfq[ty + bjp + ky][tx + bip + kx] * (1.0f / 255.0f);
                unsigned int gb = (kx < 4) ? ((glo[ky] >> (8 * kx)) & 0xFFu) : ghib[ky];
                float gv = (float)gb * (1.0f / 255.0f);
                float zd = gv - fv;
                a  += dx * dx;
                b  += dx * dy;
                d  += dy * dy;
                pp += zd * dx;
                q  += zd * dy;
            }
        }
    }
    // avoid FMA contraction: thresholds must match the reference rounding
    float det = __fsub_rn(__fmul_rn(a, d), __fmul_rn(b, b));
    float u   = __fsub_rn(__fmul_rn(d, pp), __fmul_rn(b, q));
    float v   = __fsub_rn(__fmul_rn(a, q), __fmul_rn(b, pp));
    bool bad = (det <= 1e-7f);
    float dd = bad ? 1.0f : det;
    float sv = v / dd;   // y component
    float su = u / dd;   // x component
    if (bad || fabsf(sv) >= 1.0f) sv = 0.0f;
    if (bad || fabsf(su) >= 1.0f) su = 0.0f;

    if (z == 0) {
        int y = by + ty, x = bx + tx;
        g_fb[y * WW + x]           = A.sfb[ty + 5][tx + 5];
        g_flow1[y * WW + x]        = (float)(3 - bjp) + sv;   // -dj
        g_flow1[NPIX + y * WW + x] = (float)(3 - bip) + su;   // -di
    }

    // ================= GRID BARRIER (all 256 blocks co-resident) ==============
    __syncthreads();
    if (tid == 0) {
        unsigned int my;
        asm volatile("atom.add.release.gpu.global.u32 %0, [%1], 1;"
                     : "=r"(my) : "l"(&g_bar) : "memory");
        unsigned int target = my - (my & (NBLK - 1u)) + NBLK;   // end of this replay's round
        unsigned int cur;
        do {
            asm volatile("ld.global.acquire.gpu.u32 %0, [%1];"
                         : "=r"(cur) : "l"(&g_bar) : "memory");
            if (cur >= target) break;
            __nanosleep(64);
        } while (true);
    }
    __syncthreads();   // also fences smem reuse below

    // ================= PHASE B: median + bilateral =============================
    SmemB& B = *reinterpret_cast<SmemB*>(smem_raw);

    for (int i = tid; i < 2 * 484; i += 512) {
        int ch = i >= 484;
        int rem = i - ch * 484;
        int r = rem / 22, c = rem % 22;
        int y = min(max(by - 3 + r, 0), HH - 1);
        int x = min(max(bx - 3 + c, 0), WW - 1);
        B.sflow[ch][r][c] = g_flow1[ch * NPIX + y * WW + x];
    }
    __syncthreads();

    for (int i = tid; i < 2 * 400; i += 512) {
        int ch = i >= 400;
        int rem = i - ch * 400;
        int r = rem / 20, c = rem % 20;
        int y = by - 2 + r, x = bx - 2 + c;
        bool in = (y >= 0 && y < HH && x >= 0 && x < WW);
        float m = 0.0f;
        if (in) {
            int ym = max(y - 1, 0) - (by - 3);
            int y0 = y - (by - 3);
            int yp = min(y + 1, HH - 1) - (by - 3);
            int xm = max(x - 1, 0) - (bx - 3);
            int x0 = x - (bx - 3);
            int xp = min(x + 1, WW - 1) - (bx - 3);
            const float (*fl)[22] = B.sflow[ch];
            m = median9(fl[ym][xm], fl[ym][x0], fl[ym][xp],
                        fl[y0][xm], fl[y0][x0], fl[y0][xp],
                        fl[yp][xm], fl[yp][x0], fl[yp][xp]);
        }
        B.smed[ch][r][c] = m;
        if (ch == 0) B.sguide[r][c] = in ? g_fb[y * WW + x] : 0.0f;
    }
    __syncthreads();

    {
        int pb = tid >> 1, ch = tid & 1;
        int tyb = pb >> 4, txb = pb & 15;
        const float KVAL = -1.0f / 4.5f;   // -1/(2*1.5^2)
        const float SII  = 200.0f;         //  1/(2*0.05^2)
        float c = B.sguide[tyb + 2][txb + 2];
        float wsum = 0.f, s = 0.f;
        const float (*md)[20] = B.smed[ch];
        #pragma unroll
        for (int dy = 0; dy < 5; dy++) {
            #pragma unroll
            for (int dx = 0; dx < 5; dx++) {
                float tn = B.sguide[tyb + dy][txb + dx];   // zero outside image
                float df = c - tn;
                float co = 1.0f - fabsf(KVAL - df * df * SII);
                co = fminf(fmaxf(co, 0.0f), 1.0f);
                wsum += co;                                // OOB still weighs denom
                s += md[tyb + dy][txb + dx] * co;
            }
        }
        int y = by + tyb, x = bx + txb;
        out[ch * NPIX + y * WW + x] = s / wsum;
    }
}

// ---------------- launch ----------------
extern "C" void kernel_launch(void* const* d_in, const int* in_sizes, int n_in,
                              void* d_out, int out_size) {
    const float* f = (const float*)d_in[0];
    const float* g = (const float*)d_in[1];
    float* out = (float*)d_out;

    dim3 grd(WW / 16, HH / 16);   // 256 blocks — all co-resident at 2 blocks/SM
    flow_fused<<<grd, 512>>>(f, g, out);
}

// round 7
// speedup vs baseline: 1.1212x; 1.0152x over previous
#include <cuda_runtime.h>
#include <stdint.h>

#define HH 256
#define WW 256
#define NPIX (HH*WW)
#define TW 32
#define TH 16
#define NBLK 128u

// ---------------- scratch (device globals; no allocations allowed) -------------
__device__ float g_flow1[2*NPIX];   // vector + subpixel (before median)
__device__ unsigned int g_bar;      // grid barrier counter (monotonic across replays)

// packed rank table: (spiral_rank(s) << 6) | s   for s = (dj+3)*7 + (di+3)
__constant__ int c_rank[49] = {
    (42<<6)|0,(43<<6)|1,(44<<6)|2,(45<<6)|3,(46<<6)|4,(47<<6)|5,(48<<6)|6,
    (41<<6)|7,(20<<6)|8,(21<<6)|9,(22<<6)|10,(23<<6)|11,(24<<6)|12,(25<<6)|13,
    (40<<6)|14,(19<<6)|15,(6<<6)|16,(7<<6)|17,(8<<6)|18,(9<<6)|19,(26<<6)|20,
    (39<<6)|21,(18<<6)|22,(5<<6)|23,(0<<6)|24,(1<<6)|25,(10<<6)|26,(27<<6)|27,
    (38<<6)|28,(17<<6)|29,(4<<6)|30,(3<<6)|31,(2<<6)|32,(11<<6)|33,(28<<6)|34,
    (37<<6)|35,(16<<6)|36,(15<<6)|37,(14<<6)|38,(13<<6)|39,(12<<6)|40,(29<<6)|41,
    (36<<6)|42,(35<<6)|43,(34<<6)|44,(33<<6)|45,(32<<6)|46,(31<<6)|47,(30<<6)|48
};

__device__ __forceinline__ float imload(const float* __restrict__ img, int y, int x) {
    y = min(max(y, 0), HH - 1);
    x = min(max(x, 0), WW - 1);
    return __ldg(&img[y * WW + x]);
}

__device__ __forceinline__ unsigned char quant(float v) {
    float r = rintf(v * 255.0f);          // round half-to-even, matches jnp.round
    r = fminf(fmaxf(r, 0.0f), 255.0f);
    return (unsigned char)r;
}

__device__ __forceinline__ void mnmx(float& a, float& b) {
    float t = fminf(a, b);
    b = fmaxf(a, b);
    a = t;
}
__device__ __forceinline__ float median9(float p0, float p1, float p2,
                                         float p3, float p4, float p5,
                                         float p6, float p7, float p8) {
    mnmx(p1, p2); mnmx(p4, p5); mnmx(p7, p8);
    mnmx(p0, p1); mnmx(p3, p4); mnmx(p6, p7);
    mnmx(p1, p2); mnmx(p4, p5); mnmx(p7, p8);
    mnmx(p0, p3); mnmx(p5, p8); mnmx(p4, p7);
    mnmx(p3, p6); mnmx(p1, p4); mnmx(p2, p5);
    mnmx(p4, p7); mnmx(p4, p2); mnmx(p6, p4);
    mnmx(p4, p2);
    return p4;
}

// phase-overlaid shared memory (sfb stays persistent outside the union)
struct SmemA {
    float rawf[28][44];                       // origin (by-6, bx-6)
    float vertf[26][44];                      // rows (by-5), cols (bx-6)
    alignas(16) unsigned char sfq[26][48];    // origin (by-5, bx-5); cols 42..47 zero
    alignas(16) uint32_t sfqs[26][4][13];     // shifted copies; words 0..10 used
    float rawg[22][38];                       // origin (by-3, bx-3)
    float vertg[20][38];                      // rows (by-2), cols (bx-3)
    alignas(16) unsigned char sgq[20][40];    // origin (by-2, bx-2); cols 36..39 zero
    float sdx[20][36];                        // origin (by-2, bx-2)
    float sdy[20][36];
};
struct SmemB {
    float sflow[2][22][38];   // flow, halo 3, replicate clamp; origin (by-3, bx-3)
    float smed[2][20][36];    // median flow, halo 2, zero outside; origin (by-2, bx-2)
    float sguide[20][36];     // fb guide, halo 2, zero outside
};

// =====================================================================
// One fused kernel, 128 blocks x 1024 threads (32x16 tile, 2 thr/px).
// One block per SM -> balanced single wave; software grid barrier.
// =====================================================================
__global__ __launch_bounds__(1024, 1) void flow_fused(const float* __restrict__ f,
                                                      const float* __restrict__ g,
                                                      float* __restrict__ out) {
    __shared__ float sfb[26][42];             // origin (by-5, bx-5); persists to phase B
    __shared__ __align__(16) unsigned char smem_raw[
        sizeof(SmemA) > sizeof(SmemB) ? sizeof(SmemA) : sizeof(SmemB)];
    SmemA& A = *reinterpret_cast<SmemA*>(smem_raw);

    const int bx = blockIdx.x * TW, by = blockIdx.y * TH;
    const int tid = threadIdx.x;
    const int p  = tid >> 1;          // pixel 0..511
    const int z  = tid & 1;           // dip-group
    const int ty = p >> 5, tx = p & 31;

    // ================= PHASE A =================
    for (int i = tid; i < 28 * 44; i += 1024) {
        int r = i / 44, c = i % 44;
        A.rawf[r][c] = imload(f, by - 6 + r, bx - 6 + c);
    }
    for (int i = tid; i < 22 * 38; i += 1024) {
        int r = i / 38, c = i % 38;
        A.rawg[r][c] = imload(g, by - 3 + r, bx - 3 + c);
    }
    __syncthreads();

    for (int i = tid; i < 26 * 44; i += 1024) {
        int r = i / 44, c = i % 44;
        A.vertf[r][c] = (A.rawf[r][c] + 2.0f * A.rawf[r + 1][c] + A.rawf[r + 2][c]) * 0.25f;
    }
    for (int i = tid; i < 20 * 38; i += 1024) {
        int r = i / 38, c = i % 38;
        A.vertg[r][c] = (A.rawg[r][c] + 2.0f * A.rawg[r + 1][c] + A.rawg[r + 2][c]) * 0.25f;
    }
    __syncthreads();

    for (int i = tid; i < 26 * 48; i += 1024) {
        int r = i / 48, c = i % 48;
        unsigned char v = 0;
        if (c < 42) {
            float fb = (A.vertf[r][c] + 2.0f * A.vertf[r][c + 1] + A.vertf[r][c + 2]) * 0.25f;
            sfb[r][c] = fb;
            int y = by - 5 + r, x = bx - 5 + c;
            bool in = (y >= 0 && y < HH && x >= 0 && x < WW);
            v = in ? quant(fb) : (unsigned char)0;
        }
        A.sfq[r][c] = v;
    }
    for (int i = tid; i < 20 * 40; i += 1024) {
        int r = i / 40, c = i % 40;
        unsigned char v = 0;
        if (c < 36) {
            float gb = (A.vertg[r][c] + 2.0f * A.vertg[r][c + 1] + A.vertg[r][c + 2]) * 0.25f;
            int y = by - 2 + r, x = bx - 2 + c;
            bool in = (y >= 0 && y < HH && x >= 0 && x < WW);
            v = in ? quant(gb) : (unsigned char)0;
        }
        A.sgq[r][c] = v;
    }
    __syncthreads();

    for (int i = tid; i < 26 * 44; i += 1024) {      // 26 rows x 4 shifts x 11 words
        int r = i / 44, rem = i % 44;
        int k = rem / 11, w = rem % 11;
        const uint32_t* W = (const uint32_t*)A.sfq[r];
        A.sfqs[r][k][w] = __byte_perm(W[w], W[w + 1], 0x3210u + (unsigned)k * 0x1111u);
    }
    for (int i = tid; i < 20 * 36; i += 1024) {
        int r = i / 36, c = i % 36;
        int y = by - 2 + r, x = bx - 2 + c;
        bool in = (y >= 0 && y < HH && x >= 0 && x < WW);
        float dyv = 0.0f, dxv = 0.0f;
        if (in) {
            int yn = min(y + 1, HH - 1) - (by - 5);
            int yp = max(y - 1, 0) - (by - 5);
            int xn = min(x + 1, WW - 1) - (bx - 5);
            int xp = max(x - 1, 0) - (bx - 5);
            dyv = (sfb[yn][c + 3] - sfb[yp][c + 3]) * 0.5f;
            dxv = (sfb[r + 3][xn] - sfb[r + 3][xp]) * 0.5f;
        }
        A.sdy[r][c] = dyv;
        A.sdx[r][c] = dxv;
    }
    __syncthreads();

    // g template: 5 rows (4 bytes + 1 byte), origin col tx in sgq
    unsigned int glo[5], ghib[5];
    {
        int k2 = tx & 3, w2 = tx >> 2;
        unsigned int sel = 0x3210u + (unsigned)k2 * 0x1111u;
        #pragma unroll
        for (int ky = 0; ky < 5; ky++) {
            const uint32_t* row = (const uint32_t*)A.sgq[ty + ky];
            uint32_t a = row[w2], b2 = row[w2 + 1];
            glo[ky]  = __byte_perm(a, b2, sel);
            ghib[ky] = (b2 >> (8 * k2)) & 0xFFu;
        }
    }

    // SAD over assigned dip columns (z=0: 0..3, z=1: 4..6), conflict-free loads
    int best = 0x7fffffff;
    const int dip0 = z ? 4 : 0;
    const int dip1 = z ? 7 : 4;
    for (int dip = dip0; dip < dip1; ++dip) {
        int s = tx + dip;
        int k = s & 3, wi = s >> 2;
        const uint32_t* bp = &A.sfqs[ty][k][wi];
        uint32_t flo[11], fhi[11];
        #pragma unroll
        for (int r = 0; r < 11; r++) {
            const uint32_t* rp = bp + r * 52;   // next fq row = 4*13 words
            flo[r] = rp[0];
            fhi[r] = rp[1] & 0xFFu;
        }
        #pragma unroll
        for (int djp = 0; djp < 7; djp++) {
            unsigned int sad = 0;
            #pragma unroll
            for (int ky = 0; ky < 5; ky++) {
                sad = __dp4a(__vabsdiffu4(flo[djp + ky], glo[ky]), 0x01010101u, sad);
                sad = __usad(fhi[djp + ky], ghib[ky], sad);
            }
            int packed = ((int)sad << 12) | c_rank[djp * 7 + dip];
            best = min(best, packed);
        }
    }
    best = min(best, __shfl_xor_sync(0xffffffffu, best, 1));

    int bestS = best & 63;
    int bjp = bestS / 7, bip = bestS % 7;

    // Lucas-Kanade subpixel on the 5x5 border ring
    float a = 0.f, b = 0.f, d = 0.f, pp = 0.f, q = 0.f;
    #pragma unroll
    for (int ky = 0; ky < 5; ky++) {
        #pragma unroll
        for (int kx = 0; kx < 5; kx++) {
            if (ky == 0 || ky == 4 || kx == 0 || kx == 4) {
                float dx = A.sdx[ty + ky][tx + kx];
                float dy = A.sdy[ty + ky][tx + kx];
                float fv = (float)A.sfq[ty + bjp + ky][tx + bip + kx] * (1.0f / 255.0f);
                unsigned int gb = (kx < 4) ? ((glo[ky] >> (8 * kx)) & 0xFFu) : ghib[ky];
                float gv = (float)gb * (1.0f / 255.0f);
                float zd = gv - fv;
                a  += dx * dx;
                b  += dx * dy;
                d  += dy * dy;
                pp += zd * dx;
                q  += zd * dy;
            }
        }
    }
    // avoid FMA contraction: thresholds must match the reference rounding
    float det = __fsub_rn(__fmul_rn(a, d), __fmul_rn(b, b));
    float u   = __fsub_rn(__fmul_rn(d, pp), __fmul_rn(b, q));
    float v   = __fsub_rn(__fmul_rn(a, q), __fmul_rn(b, pp));
    bool bad = (det <= 1e-7f);
    float dd = bad ? 1.0f : det;
    float sv = v / dd;   // y component
    float su = u / dd;   // x component
    if (bad || fabsf(sv) >= 1.0f) sv = 0.0f;
    if (bad || fabsf(su) >= 1.0f) su = 0.0f;

    if (z == 0) {
        int y = by + ty, x = bx + tx;
        g_flow1[y * WW + x]        = (float)(3 - bjp) + sv;   // -dj
        g_flow1[NPIX + y * WW + x] = (float)(3 - bip) + su;   // -di
    }

    // ================= GRID BARRIER (128 blocks, all co-resident) ==============
    __syncthreads();
    if (tid == 0) {
        unsigned int my;
        asm volatile("atom.add.release.gpu.global.u32 %0, [%1], 1;"
                     : "=r"(my) : "l"(&g_bar) : "memory");
        unsigned int target = my - (my & (NBLK - 1u)) + NBLK;   // end of this round
        unsigned int cur;
        do {
            asm volatile("ld.global.acquire.gpu.u32 %0, [%1];"
                         : "=r"(cur) : "l"(&g_bar) : "memory");
            if (cur >= target) break;
            __nanosleep(64);
        } while (true);
    }
    __syncthreads();   // also fences smem reuse below

    // ================= PHASE B: median + bilateral =============================
    SmemB& B = *reinterpret_cast<SmemB*>(smem_raw);

    for (int i = tid; i < 2 * 836; i += 1024) {      // 22 x 38 per channel
        int ch = i >= 836;
        int rem = i - ch * 836;
        int r = rem / 38, c = rem % 38;
        int y = min(max(by - 3 + r, 0), HH - 1);
        int x = min(max(bx - 3 + c, 0), WW - 1);
        B.sflow[ch][r][c] = g_flow1[ch * NPIX + y * WW + x];
    }
    __syncthreads();

    for (int i = tid; i < 2 * 720; i += 1024) {      // 20 x 36 per channel
        int ch = i >= 720;
        int rem = i - ch * 720;
        int r = rem / 36, c = rem % 36;
        int y = by - 2 + r, x = bx - 2 + c;
        bool in = (y >= 0 && y < HH && x >= 0 && x < WW);
        float m = 0.0f;
        if (in) {
            int ym = max(y - 1, 0) - (by - 3);
            int y0 = y - (by - 3);
            int yp = min(y + 1, HH - 1) - (by - 3);
            int xm = max(x - 1, 0) - (bx - 3);
            int x0 = x - (bx - 3);
            int xp = min(x + 1, WW - 1) - (bx - 3);
            const float (*fl)[38] = B.sflow[ch];
            m = median9(fl[ym][xm], fl[ym][x0], fl[ym][xp],
                        fl[y0][xm], fl[y0][x0], fl[y0][xp],
                        fl[yp][xm], fl[yp][x0], fl[yp][xp]);
        }
        B.smed[ch][r][c] = m;
        if (ch == 0) B.sguide[r][c] = in ? sfb[r + 3][c + 3] : 0.0f;
    }
    __syncthreads();

    {
        int ch = z;                    // 1024 threads = 512 px x 2 channels
        const float KVAL = -1.0f / 4.5f;   // -1/(2*1.5^2)
        const float SII  = 200.0f;         //  1/(2*0.05^2)
        float c = B.sguide[ty + 2][tx + 2];
        float wsum = 0.f, s = 0.f;
        const float (*md)[36] = B.smed[ch];
        #pragma unroll
        for (int dy = 0; dy < 5; dy++) {
            #pragma unroll
            for (int dx = 0; dx < 5; dx++) {
                float tn = B.sguide[ty + dy][tx + dx];   // zero outside image
                float df = c - tn;
                float co = 1.0f - fabsf(KVAL - df * df * SII);
                co = fminf(fmaxf(co, 0.0f), 1.0f);
                wsum += co;                              // OOB still weighs denom
                s += md[ty + dy][tx + dx] * co;
            }
        }
        int y = by + ty, x = bx + tx;
        out[ch * NPIX + y * WW + x] = s / wsum;
    }
}

// ---------------- launch ----------------
extern "C" void kernel_launch(void* const* d_in, const int* in_sizes, int n_in,
                              void* d_out, int out_size) {
    const float* f = (const float*)d_in[0];
    const float* g = (const float*)d_in[1];
    float* out = (float*)d_out;

    dim3 grd(WW / TW, HH / TH);   // 8 x 16 = 128 blocks, one per SM
    flow_fused<<<grd, 1024>>>(f, g, out);
}

// round 8
// speedup vs baseline: 1.2759x; 1.1379x over previous
#include <cuda_runtime.h>
#include <stdint.h>

#define HH 256
#define WW 256
#define NPIX (HH*WW)
#define TW 32
#define TH 16
#define NBLK 128u

// ---------------- scratch (device globals; no allocations allowed) -------------
__device__ float g_flow1[2*NPIX];   // vector + subpixel (before median)
__device__ unsigned int g_bar;      // grid barrier counter (monotonic across replays)

// packed rank table: (spiral_rank(s) << 6) | s   for s = (dj+3)*7 + (di+3)
__constant__ int c_rank[49] = {
    (42<<6)|0,(43<<6)|1,(44<<6)|2,(45<<6)|3,(46<<6)|4,(47<<6)|5,(48<<6)|6,
    (41<<6)|7,(20<<6)|8,(21<<6)|9,(22<<6)|10,(23<<6)|11,(24<<6)|12,(25<<6)|13,
    (40<<6)|14,(19<<6)|15,(6<<6)|16,(7<<6)|17,(8<<6)|18,(9<<6)|19,(26<<6)|20,
    (39<<6)|21,(18<<6)|22,(5<<6)|23,(0<<6)|24,(1<<6)|25,(10<<6)|26,(27<<6)|27,
    (38<<6)|28,(17<<6)|29,(4<<6)|30,(3<<6)|31,(2<<6)|32,(11<<6)|33,(28<<6)|34,
    (37<<6)|35,(16<<6)|36,(15<<6)|37,(14<<6)|38,(13<<6)|39,(12<<6)|40,(29<<6)|41,
    (36<<6)|42,(35<<6)|43,(34<<6)|44,(33<<6)|45,(32<<6)|46,(31<<6)|47,(30<<6)|48
};

__device__ __forceinline__ float imload(const float* __restrict__ img, int y, int x) {
    y = min(max(y, 0), HH - 1);
    x = min(max(x, 0), WW - 1);
    return __ldg(&img[y * WW + x]);
}

__device__ __forceinline__ unsigned char quant(float v) {
    float r = rintf(v * 255.0f);          // round half-to-even, matches jnp.round
    r = fminf(fmaxf(r, 0.0f), 255.0f);
    return (unsigned char)r;
}

__device__ __forceinline__ void mnmx(float& a, float& b) {
    float t = fminf(a, b);
    b = fmaxf(a, b);
    a = t;
}
__device__ __forceinline__ float median9(float p0, float p1, float p2,
                                         float p3, float p4, float p5,
                                         float p6, float p7, float p8) {
    mnmx(p1, p2); mnmx(p4, p5); mnmx(p7, p8);
    mnmx(p0, p1); mnmx(p3, p4); mnmx(p6, p7);
    mnmx(p1, p2); mnmx(p4, p5); mnmx(p7, p8);
    mnmx(p0, p3); mnmx(p5, p8); mnmx(p4, p7);
    mnmx(p3, p6); mnmx(p1, p4); mnmx(p2, p5);
    mnmx(p4, p7); mnmx(p4, p2); mnmx(p6, p4);
    mnmx(p4, p2);
    return p4;
}

// phase-overlaid shared memory (sfb + merge arrays persist outside the union)
struct SmemA {
    float rawf[28][64];                       // origin (by-6, bx-6), cols 0..43
    float vertf[26][64];                      // rows (by-5), cols (bx-6), 0..43
    alignas(16) unsigned char sfq[26][56];    // origin (by-5, bx-5); cols 0..41 data, 42..47 zero
    alignas(16) uint32_t sfqs[4][26][12];     // shifted copies; plane stride 312 (mod32=24)
    float rawg[22][38];                       // origin (by-3, bx-3)
    float vertg[20][38];                      // rows (by-2), cols (bx-3)
    alignas(16) unsigned char sgq[20][40];    // origin (by-2, bx-2); cols 36..39 zero
    float sdx[20][36];                        // origin (by-2, bx-2)
    float sdy[20][36];
};
struct SmemB {
    float sflow[2][22][38];   // flow, halo 3, replicate clamp; origin (by-3, bx-3)
    float smed[2][20][36];    // median flow, halo 2, zero outside; origin (by-2, bx-2)
    float sguide[20][36];     // fb guide, halo 2, zero outside
};

// =====================================================================
// One fused kernel, 128 blocks x 1024 threads (32x16 tile).
// Each pixel owned by a WARP PAIR (z = warpId&1) -> divergence-free
// work splitting for SAD / LK / bilateral, merged through smem.
// =====================================================================
__global__ __launch_bounds__(1024, 1) void flow_fused(const float* __restrict__ f,
                                                      const float* __restrict__ g,
                                                      float* __restrict__ out) {
    __shared__ float sfb[26][42];             // origin (by-5, bx-5); persists to phase B
    __shared__ int   sbest[2][16][32];
    __shared__ float sacc[5][16][32];         // LK partials (phase A) / bilateral partials (phase B)
    __shared__ __align__(16) unsigned char smem_raw[
        sizeof(SmemA) > sizeof(SmemB) ? sizeof(SmemA) : sizeof(SmemB)];
    SmemA& A = *reinterpret_cast<SmemA*>(smem_raw);

    const int bx = blockIdx.x * TW, by = blockIdx.y * TH;
    const int tid = threadIdx.x;
    const int w   = tid >> 5;
    const int z   = w & 1;            // warp-uniform work-split id
    const int ty  = w >> 1;           // pixel row 0..15
    const int tx  = tid & 31;         // pixel col 0..31

    // ================= PHASE A =================
    // raw f: 28 x 44 (pitch 64, shift/mask indexing)
    #pragma unroll
    for (int pass = 0; pass < 2; pass++) {
        int r = (pass << 4) + (tid >> 6);
        int c = tid & 63;
        if (r < 28 && c < 44) A.rawf[r][c] = imload(f, by - 6 + r, bx - 6 + c);
    }
    // raw g: 22 x 38 = 836 (single iteration)
    if (tid < 22 * 38) {
        int r = tid / 38, c = tid % 38;
        A.rawg[r][c] = imload(g, by - 3 + r, bx - 3 + c);
    }
    __syncthreads();

    // vertical binomial
    #pragma unroll
    for (int pass = 0; pass < 2; pass++) {
        int r = (pass << 4) + (tid >> 6);
        int c = tid & 63;
        if (r < 26 && c < 44)
            A.vertf[r][c] = (A.rawf[r][c] + 2.0f * A.rawf[r + 1][c] + A.rawf[r + 2][c]) * 0.25f;
    }
    if (tid < 20 * 38) {
        int r = tid / 38, c = tid % 38;
        A.vertg[r][c] = (A.rawg[r][c] + 2.0f * A.rawg[r + 1][c] + A.rawg[r + 2][c]) * 0.25f;
    }
    __syncthreads();

    // horizontal binomial + quantize
    #pragma unroll
    for (int pass = 0; pass < 2; pass++) {
        int r = (pass << 4) + (tid >> 6);
        int c = tid & 63;
        if (r < 26 && c < 48) {
            unsigned char v = 0;
            if (c < 42) {
                float fb = (A.vertf[r][c] + 2.0f * A.vertf[r][c + 1] + A.vertf[r][c + 2]) * 0.25f;
                sfb[r][c] = fb;
                int y = by - 5 + r, x = bx - 5 + c;
                bool in = (y >= 0 && y < HH && x >= 0 && x < WW);
                v = in ? quant(fb) : (unsigned char)0;
            }
            A.sfq[r][c] = v;
        }
    }
    if (tid < 20 * 40) {
        int r = tid / 40, c = tid % 40;
        unsigned char v = 0;
        if (c < 36) {
            float gb = (A.vertg[r][c] + 2.0f * A.vertg[r][c + 1] + A.vertg[r][c + 2]) * 0.25f;
            int y = by - 2 + r, x = bx - 2 + c;
            bool in = (y >= 0 && y < HH && x >= 0 && x < WW);
            v = in ? quant(gb) : (unsigned char)0;
        }
        A.sgq[r][c] = v;
    }
    __syncthreads();

    // shifted fq copies (bank-disjoint planes) + gradient of fb
    #pragma unroll
    for (int pass = 0; pass < 2; pass++) {
        int i = (pass << 10) + tid;        // 0..2047
        int r = i >> 6;                    // 0..31
        int rem = i & 63;
        int k = rem >> 4, ww = rem & 15;
        if (r < 26 && ww < 11) {
            const uint32_t* W = (const uint32_t*)A.sfq[r];
            A.sfqs[k][r][ww] = __byte_perm(W[ww], W[ww + 1], 0x3210u + (unsigned)k * 0x1111u);
        }
    }
    if (tid < 20 * 36) {
        int r = tid / 36, c = tid % 36;
        int y = by - 2 + r, x = bx - 2 + c;
        bool in = (y >= 0 && y < HH && x >= 0 && x < WW);
        float dyv = 0.0f, dxv = 0.0f;
        if (in) {
            int yn = min(y + 1, HH - 1) - (by - 5);
            int yp = max(y - 1, 0) - (by - 5);
            int xn = min(x + 1, WW - 1) - (bx - 5);
            int xp = max(x - 1, 0) - (bx - 5);
            dyv = (sfb[yn][c + 3] - sfb[yp][c + 3]) * 0.5f;
            dxv = (sfb[r + 3][xn] - sfb[r + 3][xp]) * 0.5f;
        }
        A.sdy[r][c] = dyv;
        A.sdx[r][c] = dxv;
    }
    __syncthreads();

    // g template: 5 rows (4 bytes + 1 byte) at origin col tx in sgq
    unsigned int glo[5], ghib[5];
    {
        int k2 = tx & 3, w2 = tx >> 2;
        unsigned int sel = 0x3210u + (unsigned)k2 * 0x1111u;
        #pragma unroll
        for (int ky = 0; ky < 5; ky++) {
            const uint32_t* row = (const uint32_t*)A.sgq[ty + ky];
            uint32_t a = row[w2], b2 = row[w2 + 1];
            glo[ky]  = __byte_perm(a, b2, sel);
            ghib[ky] = (b2 >> (8 * k2)) & 0xFFu;
        }
    }

    // SAD over assigned dip columns (z=0: 0..3, z=1: 4..6), bank-disjoint loads
    int best = 0x7fffffff;
    const int dipA = z ? 4 : 0;
    const int dipB = z ? 7 : 4;
    #pragma unroll 1
    for (int dip = dipA; dip < dipB; ++dip) {
        int s = tx + dip;                 // 0..37
        int k = s & 3, wi = s >> 2;
        const uint32_t* bp = &A.sfqs[k][ty][wi];
        uint32_t flo[11], fhi[11];
        #pragma unroll
        for (int r = 0; r < 11; r++) {
            flo[r] = bp[r * 12];
            fhi[r] = bp[r * 12 + 1] & 0xFFu;
        }
        #pragma unroll
        for (int djp = 0; djp < 7; djp++) {
            unsigned int sad = 0;
            #pragma unroll
            for (int ky = 0; ky < 5; ky++) {
                sad = __dp4a(__vabsdiffu4(flo[djp + ky], glo[ky]), 0x01010101u, sad);
                sad = __usad(fhi[djp + ky], ghib[ky], sad);
            }
            int packed = ((int)sad << 12) | c_rank[djp * 7 + dip];
            best = min(best, packed);
        }
    }
    sbest[z][ty][tx] = best;
    __syncthreads();
    best = min(best, sbest[z ^ 1][ty][tx]);

    int bestS = best & 63;
    int bjp = bestS / 7, bip = bestS % 7;

    // Lucas-Kanade ring, split across the warp pair (z warp-uniform -> real branch)
    {
        float a = 0.f, b = 0.f, d = 0.f, pp = 0.f, q = 0.f;
        if (z == 0) {
            #pragma unroll
            for (int ky = 0; ky < 5; ky += 4) {         // rows 0 and 4
                #pragma unroll
                for (int kx = 0; kx < 5; kx++) {
                    float dx = A.sdx[ty + ky][tx + kx];
                    float dy = A.sdy[ty + ky][tx + kx];
                    float fv = (float)A.sfq[ty + bjp + ky][tx + bip + kx] * (1.0f / 255.0f);
                    unsigned int gb = (kx < 4) ? ((glo[ky] >> (8 * kx)) & 0xFFu) : ghib[ky];
                    float gv = (float)gb * (1.0f / 255.0f);
                    float zd = gv - fv;
                    a += dx * dx; b += dx * dy; d += dy * dy;
                    pp += zd * dx; q += zd * dy;
                }
            }
        } else {
            #pragma unroll
            for (int ky = 1; ky < 4; ky++) {            // rows 1..3, side columns
                #pragma unroll
                for (int kx = 0; kx < 5; kx += 4) {
                    float dx = A.sdx[ty + ky][tx + kx];
                    float dy = A.sdy[ty + ky][tx + kx];
                    float fv = (float)A.sfq[ty + bjp + ky][tx + bip + kx] * (1.0f / 255.0f);
                    unsigned int gb = (kx < 4) ? ((glo[ky] >> (8 * kx)) & 0xFFu) : ghib[ky];
                    float gv = (float)gb * (1.0f / 255.0f);
                    float zd = gv - fv;
                    a += dx * dx; b += dx * dy; d += dy * dy;
                    pp += zd * dx; q += zd * dy;
                }
            }
            sacc[0][ty][tx] = a;  sacc[1][ty][tx] = b;  sacc[2][ty][tx] = d;
            sacc[3][ty][tx] = pp; sacc[4][ty][tx] = q;
        }
        __syncthreads();
        if (z == 0) {
            a  += sacc[0][ty][tx]; b += sacc[1][ty][tx]; d += sacc[2][ty][tx];
            pp += sacc[3][ty][tx]; q += sacc[4][ty][tx];
            // avoid FMA contraction: thresholds must match the reference rounding
            float det = __fsub_rn(__fmul_rn(a, d), __fmul_rn(b, b));
            float u   = __fsub_rn(__fmul_rn(d, pp), __fmul_rn(b, q));
            float v   = __fsub_rn(__fmul_rn(a, q), __fmul_rn(b, pp));
            bool bad = (det <= 1e-7f);
            float dd = bad ? 1.0f : det;
            float sv = v / dd;   // y component
            float su = u / dd;   // x component
            if (bad || fabsf(sv) >= 1.0f) sv = 0.0f;
            if (bad || fabsf(su) >= 1.0f) su = 0.0f;
            int y = by + ty, x = bx + tx;
            g_flow1[y * WW + x]        = (float)(3 - bjp) + sv;   // -dj
            g_flow1[NPIX + y * WW + x] = (float)(3 - bip) + su;   // -di
        }
    }

    // ================= GRID BARRIER (128 blocks, all co-resident) ==============
    __syncthreads();
    if (tid == 0) {
        unsigned int my;
        asm volatile("atom.add.release.gpu.global.u32 %0, [%1], 1;"
                     : "=r"(my) : "l"(&g_bar) : "memory");
        unsigned int target = my - (my & (NBLK - 1u)) + NBLK;   // end of this round
        unsigned int cur;
        do {
            asm volatile("ld.global.acquire.gpu.u32 %0, [%1];"
                         : "=r"(cur) : "l"(&g_bar) : "memory");
            if (cur >= target) break;
            __nanosleep(64);
        } while (true);
    }
    __syncthreads();   // also fences smem reuse below

    // ================= PHASE B: median + bilateral =============================
    SmemB& B = *reinterpret_cast<SmemB*>(smem_raw);

    for (int i = tid; i < 2 * 836; i += 1024) {      // 22 x 38 per channel
        int ch = i >= 836;
        int rem = i - ch * 836;
        int r = rem / 38, c = rem % 38;
        int y = min(max(by - 3 + r, 0), HH - 1);
        int x = min(max(bx - 3 + c, 0), WW - 1);
        B.sflow[ch][r][c] = g_flow1[ch * NPIX + y * WW + x];
    }
    __syncthreads();

    for (int i = tid; i < 2 * 720; i += 1024) {      // 20 x 36 per channel
        int ch = i >= 720;
        int rem = i - ch * 720;
        int r = rem / 36, c = rem % 36;
        int y = by - 2 + r, x = bx - 2 + c;
        bool in = (y >= 0 && y < HH && x >= 0 && x < WW);
        float m = 0.0f;
        if (in) {
            int ym = max(y - 1, 0) - (by - 3);
            int y0 = y - (by - 3);
            int yp = min(y + 1, HH - 1) - (by - 3);
            int xm = max(x - 1, 0) - (bx - 3);
            int x0 = x - (bx - 3);
            int xp = min(x + 1, WW - 1) - (bx - 3);
            const float (*fl)[38] = B.sflow[ch];
            m = median9(fl[ym][xm], fl[ym][x0], fl[ym][xp],
                        fl[y0][xm], fl[y0][x0], fl[y0][xp],
                        fl[yp][xm], fl[yp][x0], fl[yp][xp]);
        }
        B.smed[ch][r][c] = m;
        if (ch == 0) B.sguide[r][c] = in ? sfb[r + 3][c + 3] : 0.0f;
    }
    __syncthreads();

    // bilateral, tap-split across the warp pair (13 + 12 taps)
    {
        const float KVAL = -1.0f / 4.5f;   // -1/(2*1.5^2)
        const float SII  = 200.0f;         //  1/(2*0.05^2)
        float c = B.sguide[ty + 2][tx + 2];
        float wsum = 0.f, s0 = 0.f, s1 = 0.f;

        #define BTAP(dy, dx) { \
            float tn = B.sguide[ty + (dy)][tx + (dx)]; \
            float df = c - tn; \
            float co = 1.0f - fabsf(KVAL - df * df * SII); \
            co = fminf(fmaxf(co, 0.0f), 1.0f); \
            wsum += co; \
            s0 += B.smed[0][ty + (dy)][tx + (dx)] * co; \
            s1 += B.smed[1][ty + (dy)][tx + (dx)] * co; }

        if (z == 0) {
            #pragma unroll
            for (int dy = 0; dy < 2; dy++)
                #pragma unroll
                for (int dx = 0; dx < 5; dx++) BTAP(dy, dx);
            BTAP(2, 0); BTAP(2, 1); BTAP(2, 2);
        } else {
            BTAP(2, 3); BTAP(2, 4);
            #pragma unroll
            for (int dy = 3; dy < 5; dy++)
                #pragma unroll
                for (int dx = 0; dx < 5; dx++) BTAP(dy, dx);
            sacc[0][ty][tx] = wsum;
            sacc[1][ty][tx] = s0;
            sacc[2][ty][tx] = s1;
        }
        #undef BTAP
        __syncthreads();
        if (z == 0) {
            wsum += sacc[0][ty][tx];
            s0   += sacc[1][ty][tx];
            s1   += sacc[2][ty][tx];
            int y = by + ty, x = bx + tx;
            out[y * WW + x]        = s0 / wsum;
            out[NPIX + y * WW + x] = s1 / wsum;
        }
    }
}

// ---------------- launch ----------------
extern "C" void kernel_launch(void* const* d_in, const int* in_sizes, int n_in,
                              void* d_out, int out_size) {
    const float* f = (const float*)d_in[0];
    const float* g = (const float*)d_in[1];
    float* out = (float*)d_out;

    dim3 grd(WW / TW, HH / TH);   // 8 x 16 = 128 blocks, one per SM
    flow_fused<<<grd, 1024>>>(f, g, out);
}

// round 9
// speedup vs baseline: 1.2786x; 1.0022x over previous
#include <cuda_runtime.h>
#include <stdint.h>

#define HH 256
#define WW 256
#define NPIX (HH*WW)
#define TW 32
#define TH 16
#define NBLK 128u

// ---------------- scratch (device globals; no allocations allowed) -------------
__device__ float g_flow1[2*NPIX];   // vector + subpixel (before median)
__device__ unsigned int g_bar;      // grid barrier counter (monotonic across replays)

// packed rank table: (spiral_rank(s) << 6) | s   for s = (dj+3)*7 + (di+3)
__constant__ int c_rank[49] = {
    (42<<6)|0,(43<<6)|1,(44<<6)|2,(45<<6)|3,(46<<6)|4,(47<<6)|5,(48<<6)|6,
    (41<<6)|7,(20<<6)|8,(21<<6)|9,(22<<6)|10,(23<<6)|11,(24<<6)|12,(25<<6)|13,
    (40<<6)|14,(19<<6)|15,(6<<6)|16,(7<<6)|17,(8<<6)|18,(9<<6)|19,(26<<6)|20,
    (39<<6)|21,(18<<6)|22,(5<<6)|23,(0<<6)|24,(1<<6)|25,(10<<6)|26,(27<<6)|27,
    (38<<6)|28,(17<<6)|29,(4<<6)|30,(3<<6)|31,(2<<6)|32,(11<<6)|33,(28<<6)|34,
    (37<<6)|35,(16<<6)|36,(15<<6)|37,(14<<6)|38,(13<<6)|39,(12<<6)|40,(29<<6)|41,
    (36<<6)|42,(35<<6)|43,(34<<6)|44,(33<<6)|45,(32<<6)|46,(31<<6)|47,(30<<6)|48
};

__device__ __forceinline__ float imload(const float* __restrict__ img, int y, int x) {
    y = min(max(y, 0), HH - 1);
    x = min(max(x, 0), WW - 1);
    return __ldg(&img[y * WW + x]);
}

__device__ __forceinline__ unsigned char quant(float v) {
    float r = rintf(v * 255.0f);          // round half-to-even, matches jnp.round
    r = fminf(fmaxf(r, 0.0f), 255.0f);
    return (unsigned char)r;
}

__device__ __forceinline__ void mnmx(float& a, float& b) {
    float t = fminf(a, b);
    b = fmaxf(a, b);
    a = t;
}
__device__ __forceinline__ float median9(float p0, float p1, float p2,
                                         float p3, float p4, float p5,
                                         float p6, float p7, float p8) {
    mnmx(p1, p2); mnmx(p4, p5); mnmx(p7, p8);
    mnmx(p0, p1); mnmx(p3, p4); mnmx(p6, p7);
    mnmx(p1, p2); mnmx(p4, p5); mnmx(p7, p8);
    mnmx(p0, p3); mnmx(p5, p8); mnmx(p4, p7);
    mnmx(p3, p6); mnmx(p1, p4); mnmx(p2, p5);
    mnmx(p4, p7); mnmx(p4, p2); mnmx(p6, p4);
    mnmx(p4, p2);
    return p4;
}

// phase-overlaid shared memory (sfb + merge arrays persist outside the union)
struct SmemA {
    float rawf[28][64];                       // origin (by-6, bx-6), cols 0..43
    float vertf[26][64];                      // rows (by-5), cols (bx-6), 0..43
    alignas(16) unsigned char sfq[26][56];    // origin (by-5, bx-5); cols 0..41 data, 42..47 zero
    alignas(16) uint32_t sfqs[4][26][12];     // shifted copies; plane stride 312 (mod32=24)
    float rawg[22][38];                       // origin (by-3, bx-3)
    float vertg[20][38];                      // rows (by-2), cols (bx-3)
    alignas(16) unsigned char sgq[20][40];    // origin (by-2, bx-2); cols 36..39 zero
    float sdx[20][36];                        // origin (by-2, bx-2)
    float sdy[20][36];
};
struct SmemB {
    float sflow[2][22][38];   // flow, halo 3, replicate clamp; origin (by-3, bx-3)
    float smed[2][20][36];    // median flow, halo 2, zero outside; origin (by-2, bx-2)
    float sguide[20][36];     // fb guide, halo 2, zero outside
};

// =====================================================================
// One fused kernel, 128 blocks x 1024 threads (32x16 tile).
// Warp-range-split prep (f: warps 0-19, g: warps 20-31); pixel owned by
// a warp pair (z = warpId&1); software grid barrier; halo-only reload.
// =====================================================================
__global__ __launch_bounds__(1024, 1) void flow_fused(const float* __restrict__ f,
                                                      const float* __restrict__ g,
                                                      float* __restrict__ out) {
    __shared__ float sfb[26][42];             // origin (by-5, bx-5); persists to phase B
    __shared__ int   sbest[2][16][32];
    __shared__ float sacc[5][16][32];         // LK partials / bilateral partials
    __shared__ __align__(16) unsigned char smem_raw[
        sizeof(SmemA) > sizeof(SmemB) ? sizeof(SmemA) : sizeof(SmemB)];
    SmemA& A = *reinterpret_cast<SmemA*>(smem_raw);
    SmemB& B = *reinterpret_cast<SmemB*>(smem_raw);

    const int bx = blockIdx.x * TW, by = blockIdx.y * TH;
    const int tid = threadIdx.x;
    const int w   = tid >> 5;
    const int z   = w & 1;            // warp-uniform work-split id
    const int ty  = w >> 1;           // pixel row 0..15
    const int tx  = tid & 31;         // pixel col 0..31
    const bool fgrp = (w < 20);       // prep pipeline split
    const int ft = tid;               // 0..639 in f-group
    const int gt = tid - 640;         // 0..383 in g-group

    // ================= PHASE A prep: f-warps and g-warps run concurrently ======
    if (fgrp) {
        for (int i = ft; i < 28 * 44; i += 640) {
            int r = i / 44, c = i % 44;
            A.rawf[r][c] = imload(f, by - 6 + r, bx - 6 + c);
        }
    } else {
        for (int i = gt; i < 22 * 38; i += 384) {
            int r = i / 38, c = i % 38;
            A.rawg[r][c] = imload(g, by - 3 + r, bx - 3 + c);
        }
    }
    __syncthreads();

    if (fgrp) {
        for (int i = ft; i < 26 * 44; i += 640) {
            int r = i / 44, c = i % 44;
            A.vertf[r][c] = (A.rawf[r][c] + 2.0f * A.rawf[r + 1][c] + A.rawf[r + 2][c]) * 0.25f;
        }
    } else {
        for (int i = gt; i < 20 * 38; i += 384) {
            int r = i / 38, c = i % 38;
            A.vertg[r][c] = (A.rawg[r][c] + 2.0f * A.rawg[r + 1][c] + A.rawg[r + 2][c]) * 0.25f;
        }
    }
    __syncthreads();

    if (fgrp) {
        for (int i = ft; i < 26 * 48; i += 640) {
            int r = i / 48, c = i % 48;
            unsigned char v = 0;
            if (c < 42) {
                float fb = (A.vertf[r][c] + 2.0f * A.vertf[r][c + 1] + A.vertf[r][c + 2]) * 0.25f;
                sfb[r][c] = fb;
                int y = by - 5 + r, x = bx - 5 + c;
                bool in = (y >= 0 && y < HH && x >= 0 && x < WW);
                v = in ? quant(fb) : (unsigned char)0;
            }
            A.sfq[r][c] = v;
        }
    } else {
        for (int i = gt; i < 20 * 40; i += 384) {
            int r = i / 40, c = i % 40;
            unsigned char v = 0;
            if (c < 36) {
                float gb = (A.vertg[r][c] + 2.0f * A.vertg[r][c + 1] + A.vertg[r][c + 2]) * 0.25f;
                int y = by - 2 + r, x = bx - 2 + c;
                bool in = (y >= 0 && y < HH && x >= 0 && x < WW);
                v = in ? quant(gb) : (unsigned char)0;
            }
            A.sgq[r][c] = v;
        }
    }
    __syncthreads();

    if (fgrp) {
        for (int i = ft; i < 26 * 44; i += 640) {   // 26 rows x 4 shifts x 11 words
            int r = i / 44, rem = i % 44;
            int k = rem / 11, ww = rem % 11;
            const uint32_t* W = (const uint32_t*)A.sfq[r];
            A.sfqs[k][r][ww] = __byte_perm(W[ww], W[ww + 1], 0x3210u + (unsigned)k * 0x1111u);
        }
    } else {
        for (int i = gt; i < 20 * 36; i += 384) {   // gradient of fb (f-data is ready)
            int r = i / 36, c = i % 36;
            int y = by - 2 + r, x = bx - 2 + c;
            bool in = (y >= 0 && y < HH && x >= 0 && x < WW);
            float dyv = 0.0f, dxv = 0.0f;
            if (in) {
                int yn = min(y + 1, HH - 1) - (by - 5);
                int yp = max(y - 1, 0) - (by - 5);
                int xn = min(x + 1, WW - 1) - (bx - 5);
                int xp = max(x - 1, 0) - (bx - 5);
                dyv = (sfb[yn][c + 3] - sfb[yp][c + 3]) * 0.5f;
                dxv = (sfb[r + 3][xn] - sfb[r + 3][xp]) * 0.5f;
            }
            A.sdy[r][c] = dyv;
            A.sdx[r][c] = dxv;
        }
    }
    __syncthreads();

    // g template: 5 rows (4 bytes + 1 byte) at origin col tx in sgq
    unsigned int glo[5], ghib[5];
    {
        int k2 = tx & 3, w2 = tx >> 2;
        unsigned int sel = 0x3210u + (unsigned)k2 * 0x1111u;
        #pragma unroll
        for (int ky = 0; ky < 5; ky++) {
            const uint32_t* row = (const uint32_t*)A.sgq[ty + ky];
            uint32_t a = row[w2], b2 = row[w2 + 1];
            glo[ky]  = __byte_perm(a, b2, sel);
            ghib[ky] = (b2 >> (8 * k2)) & 0xFFu;
        }
    }

    // SAD: z0 -> dips 0..2 (also does LK merge+solve later), z1 -> dips 3..6
    int best = 0x7fffffff;
    const int dipA = z ? 3 : 0;
    const int dipB = z ? 7 : 3;
    #pragma unroll 1
    for (int dip = dipA; dip < dipB; ++dip) {
        int s = tx + dip;                 // 0..37
        int k = s & 3, wi = s >> 2;
        const uint32_t* bp = &A.sfqs[k][ty][wi];
        uint32_t flo[11], fhi[11];
        #pragma unroll
        for (int r = 0; r < 11; r++) {
            flo[r] = bp[r * 12];
            fhi[r] = bp[r * 12 + 1] & 0xFFu;
        }
        #pragma unroll
        for (int djp = 0; djp < 7; djp++) {
            unsigned int sad = 0;
            #pragma unroll
            for (int ky = 0; ky < 5; ky++) {
                sad = __dp4a(__vabsdiffu4(flo[djp + ky], glo[ky]), 0x01010101u, sad);
                sad = __usad(fhi[djp + ky], ghib[ky], sad);
            }
            int packed = ((int)sad << 12) | c_rank[djp * 7 + dip];
            best = min(best, packed);
        }
    }
    sbest[z][ty][tx] = best;
    __syncthreads();
    best = min(best, sbest[z ^ 1][ty][tx]);

    int bestS = best & 63;
    int bjp = bestS / 7, bip = bestS % 7;

    // Lucas-Kanade ring, split across the warp pair; z0 merges + solves + stages
    float sv, su;   // live across the grid barrier on z0 threads
    {
        float a = 0.f, b = 0.f, d = 0.f, pp = 0.f, q = 0.f;
        if (z == 0) {
            #pragma unroll
            for (int ky = 0; ky < 5; ky += 4) {         // rows 0 and 4
                #pragma unroll
                for (int kx = 0; kx < 5; kx++) {
                    float dx = A.sdx[ty + ky][tx + kx];
                    float dy = A.sdy[ty + ky][tx + kx];
                    float fv = (float)A.sfq[ty + bjp + ky][tx + bip + kx] * (1.0f / 255.0f);
                    unsigned int gb = (kx < 4) ? ((glo[ky] >> (8 * kx)) & 0xFFu) : ghib[ky];
                    float gv = (float)gb * (1.0f / 255.0f);
                    float zd = gv - fv;
                    a += dx * dx; b += dx * dy; d += dy * dy;
                    pp += zd * dx; q += zd * dy;
                }
            }
        } else {
            #pragma unroll
            for (int ky = 1; ky < 4; ky++) {            // rows 1..3, side columns
                #pragma unroll
                for (int kx = 0; kx < 5; kx += 4) {
                    float dx = A.sdx[ty + ky][tx + kx];
                    float dy = A.sdy[ty + ky][tx + kx];
                    float fv = (float)A.sfq[ty + bjp + ky][tx + bip + kx] * (1.0f / 255.0f);
                    unsigned int gb = (kx < 4) ? ((glo[ky] >> (8 * kx)) & 0xFFu) : ghib[ky];
                    float gv = (float)gb * (1.0f / 255.0f);
                    float zd = gv - fv;
                    a += dx * dx; b += dx * dy; d += dy * dy;
                    pp += zd * dx; q += zd * dy;
                }
            }
            sacc[0][ty][tx] = a;  sacc[1][ty][tx] = b;  sacc[2][ty][tx] = d;
            sacc[3][ty][tx] = pp; sacc[4][ty][tx] = q;
        }
        __syncthreads();   // after this, ALL phase-A smem reads are complete
        if (z == 0) {
            a  += sacc[0][ty][tx]; b += sacc[1][ty][tx]; d += sacc[2][ty][tx];
            pp += sacc[3][ty][tx]; q += sacc[4][ty][tx];
            // avoid FMA contraction: thresholds must match the reference rounding
            float det = __fsub_rn(__fmul_rn(a, d), __fmul_rn(b, b));
            float u   = __fsub_rn(__fmul_rn(d, pp), __fmul_rn(b, q));
            float v   = __fsub_rn(__fmul_rn(a, q), __fmul_rn(b, pp));
            bool bad = (det <= 1e-7f);
            float dd = bad ? 1.0f : det;
            sv = v / dd;   // y component
            su = u / dd;   // x component
            if (bad || fabsf(sv) >= 1.0f) sv = 0.0f;
            if (bad || fabsf(su) >= 1.0f) su = 0.0f;
            sv += (float)(3 - bjp);   // -dj + subpixel
            su += (float)(3 - bip);   // -di + subpixel
            int y = by + ty, x = bx + tx;
            g_flow1[y * WW + x]        = sv;
            g_flow1[NPIX + y * WW + x] = su;
            // stage own interior directly into phase-B smem (A is dead now)
            B.sflow[0][ty + 3][tx + 3] = sv;
            B.sflow[1][ty + 3][tx + 3] = su;
        }
    }

    // ================= GRID BARRIER (128 blocks, all co-resident) ==============
    __syncthreads();
    if (tid == 0) {
        unsigned int my;
        asm volatile("atom.add.release.gpu.global.u32 %0, [%1], 1;"
                     : "=r"(my) : "l"(&g_bar) : "memory");
        unsigned int target = my - (my & (NBLK - 1u)) + NBLK;   // end of this round
        unsigned int cur;
        do {
            asm volatile("ld.global.acquire.gpu.u32 %0, [%1];"
                         : "=r"(cur) : "l"(&g_bar) : "memory");
            if (cur >= target) break;
            __nanosleep(64);
        } while (true);
    }
    __syncthreads();

    // ================= PHASE B: median + bilateral =============================
    // load ONLY the halo ring (22x38 minus the staged 16x32 interior)
    if (tid < 648) {
        int ch = tid >= 324;
        int i = tid - ch * 324;
        int r, c;
        if (i < 114)      { r = i / 38;              c = i % 38; }
        else if (i < 228) { int j = i - 114; r = 19 + j / 38; c = j % 38; }
        else if (i < 276) { int j = i - 228; r = 3 + j / 3;   c = j % 3; }
        else              { int j = i - 276; r = 3 + j / 3;   c = 35 + j % 3; }
        int y = min(max(by - 3 + r, 0), HH - 1);
        int x = min(max(bx - 3 + c, 0), WW - 1);
        B.sflow[ch][r][c] = g_flow1[ch * NPIX + y * WW + x];
    }
    __syncthreads();

    for (int i = tid; i < 2 * 720; i += 1024) {      // 20 x 36 per channel
        int ch = i >= 720;
        int rem = i - ch * 720;
        int r = rem / 36, c = rem % 36;
        int y = by - 2 + r, x = bx - 2 + c;
        bool in = (y >= 0 && y < HH && x >= 0 && x < WW);
        float m = 0.0f;
        if (in) {
            int ym = max(y - 1, 0) - (by - 3);
            int y0 = y - (by - 3);
            int yp = min(y + 1, HH - 1) - (by - 3);
            int xm = max(x - 1, 0) - (bx - 3);
            int x0 = x - (bx - 3);
            int xp = min(x + 1, WW - 1) - (bx - 3);
            const float (*fl)[38] = B.sflow[ch];
            m = median9(fl[ym][xm], fl[ym][x0], fl[ym][xp],
                        fl[y0][xm], fl[y0][x0], fl[y0][xp],
                        fl[yp][xm], fl[yp][x0], fl[yp][xp]);
        }
        B.smed[ch][r][c] = m;
        if (ch == 0) B.sguide[r][c] = in ? sfb[r + 3][c + 3] : 0.0f;
    }
    __syncthreads();

    // bilateral, tap-split across the warp pair (13 + 12 taps)
    {
        const float KVAL = -1.0f / 4.5f;   // -1/(2*1.5^2)
        const float SII  = 200.0f;         //  1/(2*0.05^2)
        float c = B.sguide[ty + 2][tx + 2];
        float wsum = 0.f, s0 = 0.f, s1 = 0.f;

        #define BTAP(dy, dx) { \
            float tn = B.sguide[ty + (dy)][tx + (dx)]; \
            float df = c - tn; \
            float co = 1.0f - fabsf(KVAL - df * df * SII); \
            co = fminf(fmaxf(co, 0.0f), 1.0f); \
            wsum += co; \
            s0 += B.smed[0][ty + (dy)][tx + (dx)] * co; \
            s1 += B.smed[1][ty + (dy)][tx + (dx)] * co; }

        if (z == 0) {
            #pragma unroll
            for (int dy = 0; dy < 2; dy++)
                #pragma unroll
                for (int dx = 0; dx < 5; dx++) BTAP(dy, dx);
            BTAP(2, 0); BTAP(2, 1); BTAP(2, 2);
        } else {
            BTAP(2, 3); BTAP(2, 4);
            #pragma unroll
            for (int dy = 3; dy < 5; dy++)
                #pragma unroll
                for (int dx = 0; dx < 5; dx++) BTAP(dy, dx);
            sacc[0][ty][tx] = wsum;
            sacc[1][ty][tx] = s0;
            sacc[2][ty][tx] = s1;
        }
        #undef BTAP
        __syncthreads();
        if (z == 0) {
            wsum += sacc[0][ty][tx];
            s0   += sacc[1][ty][tx];
            s1   += sacc[2][ty][tx];
            int y = by + ty, x = bx + tx;
            out[y * WW + x]        = s0 / wsum;
            out[NPIX + y * WW + x] = s1 / wsum;
        }
    }
}

// ---------------- launch ----------------
extern "C" void kernel_launch(void* const* d_in, const int* in_sizes, int n_in,
                              void* d_out, int out_size) {
    const float* f = (const float*)d_in[0];
    const float* g = (const float*)d_in[1];
    float* out = (float*)d_out;

    dim3 grd(WW / TW, HH / TH);   // 8 x 16 = 128 blocks, one per SM
    flow_fused<<<grd, 1024>>>(f, g, out);
}